// round 17
// baseline (speedup 1.0000x reference)
#include <cuda_runtime.h>
#include <cstdint>

typedef unsigned long long ull;

// Problem constants
#define BATCH   512
#define OUTF    1024
#define KDIM    128      // NUM_BLOCKS * LATTICE_DIM
#define NIDX    256      // MAX_INDICES

// Tiling for main kernel
#define NSEG    8        // k-segments (grid.y)
#define KSEG    16       // k per segment
#define KCH     2        // k per staging chunk (per buffer)
#define NCH     (KSEG / KCH)       // 8 chunks
#define BT      32       // b per CTA
#define MTHREADS 1024    // 32 warps: warp w owns o = w*32 .. w*32+31
#define BUF_F   (KCH * 32 * 256)   // floats per buffer = 16384 (64 KB)
#define BUF_P   (BUF_F / 2)        // float2 pairs per buffer
#define JT_U64  (32 * 64)          // index table: [warp][chunk(8)][group(8)] u64 = 16 KB

// ---------------- zero-init of out (poisoned by harness) ----------------
__global__ void zero_out_kernel(float4* __restrict__ out4) {
    out4[blockIdx.x * 256 + threadIdx.x] = make_float4(0.f, 0.f, 0.f, 0.f);
}

// ---------------- main kernel: gather + in-smem transpose + RED.ADD epilogue ----------------
// CTA (btile, seg): b in [btile*32,+32), k in [seg*16,+16), all 1024 o.
// smem buffers: S[buf][kk][b][ j ^ b ]; gather with lane==b is bank-conflict-free.
// Index distribution: per-warp u64 table read as LDS.64 same-address broadcasts.
// Epilogue: acc tile (32 b x 1024 o = 128 KB) transposed through the (now free)
// buffers with XOR swizzle, then coalesced RED.ADD.F32 into out[b][o].
__global__ __launch_bounds__(MTHREADS, 1) void lut_main(
    const int*   __restrict__ inp,   // [BATCH, KDIM] int32
    const int*   __restrict__ wgt,   // [OUTF, KDIM]  int32
    const float* __restrict__ lut,   // [256, 256]
    float*       __restrict__ out)   // [BATCH, OUTF]
{
    extern __shared__ ull SMEM[];             // 16 KB jt + 128 KB buffers
    ull*   jt  = SMEM;                        // [warp][c][g] u64
    float* S   = (float*)(SMEM + JT_U64);     // 2 * BUF_F floats

    const int btile = blockIdx.x;    // 0..15
    const int seg   = blockIdx.y;    // 0..7
    const int tid   = threadIdx.x;
    const int wid   = tid >> 5;
    const int lane  = tid & 31;
    const int obase = wid * 32;

    // ---- build index table: lane l scatters its 16 clipped bytes (o = obase+l) ----
    {
        const int* wp = wgt + (obase + lane) * KDIM + seg * KSEG;
        char* jt8 = (char*)(jt + wid * 64) + (lane >> 2) * 8 + (lane & 3);
        #pragma unroll
        for (int q = 0; q < 4; ++q) {
            int4 v = ((const int4*)wp)[q];
            int b0v = min(max(v.x, 0), NIDX - 1);
            int b1v = min(max(v.y, 0), NIDX - 1);
            int b2v = min(max(v.z, 0), NIDX - 1);
            int b3v = min(max(v.w, 0), NIDX - 1);
            jt8[(2 * q + 0) * 64 + 0] = (char)b0v;   // k'=4q+0: c=2q,   kk=0
            jt8[(2 * q + 0) * 64 + 4] = (char)b1v;   // k'=4q+1: c=2q,   kk=1
            jt8[(2 * q + 1) * 64 + 0] = (char)b2v;   // k'=4q+2: c=2q+1, kk=0
            jt8[(2 * q + 1) * 64 + 4] = (char)b3v;   // k'=4q+3: c=2q+1, kk=1
        }
    }

    // ---- staging assignment: warp stages 2 rows (kk fixed, b0 and b0+1) per chunk ----
    const int kw = wid >> 4;              // kk within chunk: 0 or 1
    const int b0 = (wid & 15) * 2;        // even
    const int* ip0 = inp + (btile * BT + b0) * KDIM + seg * KSEG + kw;
    float2* drow0p = (float2*)(S + (kw * 32 + b0) * 256);   // + buf*BUF_P; row b1 = +128 pairs

    // pair slots (same for both rows; computed with even b0)
    const int j0 = 4 * lane, j1 = 128 + 4 * lane;
    const int sl0 = ((j0    ) ^ b0) >> 1;
    const int sl1 = ((j0 + 2) ^ b0) >> 1;
    const int sl2 = ((j1    ) ^ b0) >> 1;
    const int sl3 = ((j1 + 2) ^ b0) >> 1;

    float acc[32];
    #pragma unroll
    for (int i = 0; i < 32; ++i) acc[i] = 0.f;

    // ---- prologue: stage chunk 0 into buffer 0 ----
    {
        int r0 = min(max(ip0[0], 0), NIDX - 1);
        int r1 = min(max(ip0[KDIM], 0), NIDX - 1);
        const float4* s0 = (const float4*)(lut + r0 * 256);
        const float4* s1 = (const float4*)(lut + r1 * 256);
        float4 a0 = s0[lane], a1 = s0[32 + lane];
        float4 c0 = s1[lane], c1 = s1[32 + lane];
        drow0p[sl0] = make_float2(a0.x, a0.y);
        drow0p[sl1] = make_float2(a0.z, a0.w);
        drow0p[sl2] = make_float2(a1.x, a1.y);
        drow0p[sl3] = make_float2(a1.z, a1.w);
        drow0p[sl0 + 128] = make_float2(c0.y, c0.x);   // odd b: swapped pair
        drow0p[sl1 + 128] = make_float2(c0.w, c0.z);
        drow0p[sl2 + 128] = make_float2(c1.y, c1.x);
        drow0p[sl3 + 128] = make_float2(c1.w, c1.z);
    }
    __syncthreads();   // jt + chunk 0 visible

    // ---- pipelined chunks ----
    #pragma unroll 1
    for (int c = 0; c < NCH; ++c) {
        const bool more = (c < NCH - 1);
        const float4* sA = (const float4*)lut;
        const float4* sB = (const float4*)lut;
        if (more) {
            int r0 = min(max(ip0[(c + 1) * KCH], 0), NIDX - 1);
            int r1 = min(max(ip0[(c + 1) * KCH + KDIM], 0), NIDX - 1);
            sA = (const float4*)(lut + r0 * 256);
            sB = (const float4*)(lut + r1 * 256);
        }

        const float* Sb = S + (c & 1) * BUF_F + lane * 256;
        const ull* jrow = jt + wid * 64 + c * 8;   // 8 broadcast words for this chunk

        float4 r0v, r1v;
        if (more) { r0v = sA[lane]; r1v = sA[32 + lane]; }   // LDG.128 row A

        ull u = jrow[0];                     // LDS.64 broadcast (1 wf)
        // gather oo = 0..15 (groups 0..3), one-group prefetch
        #pragma unroll
        for (int g = 0; g < 4; ++g) {
            ull un = jrow[g + 1];
            unsigned lo = (unsigned)u, hi = (unsigned)(u >> 32);
            #pragma unroll
            for (int i = 0; i < 4; ++i) {
                unsigned a = ((lo >> (8 * i)) & 255u) ^ (unsigned)lane;
                unsigned b = ((hi >> (8 * i)) & 255u) ^ (unsigned)lane;
                acc[4 * g + i] += Sb[a] + Sb[8192 + b];
            }
            u = un;
        }

        if (more) {
            // STS.64 row A, then LDG.128 row B into the same registers
            float2* dA0 = drow0p + ((c + 1) & 1) * BUF_P;
            dA0[sl0] = make_float2(r0v.x, r0v.y);
            dA0[sl1] = make_float2(r0v.z, r0v.w);
            dA0[sl2] = make_float2(r1v.x, r1v.y);
            dA0[sl3] = make_float2(r1v.z, r1v.w);
            r0v = sB[lane]; r1v = sB[32 + lane];
        }

        // gather oo = 16..31 (groups 4..7)
        #pragma unroll
        for (int g = 4; g < 8; ++g) {
            ull un = (g < 7) ? jrow[g + 1] : 0ull;
            unsigned lo = (unsigned)u, hi = (unsigned)(u >> 32);
            #pragma unroll
            for (int i = 0; i < 4; ++i) {
                unsigned a = ((lo >> (8 * i)) & 255u) ^ (unsigned)lane;
                unsigned b = ((hi >> (8 * i)) & 255u) ^ (unsigned)lane;
                acc[4 * g + i] += Sb[a] + Sb[8192 + b];
            }
            u = un;
        }

        if (more) {
            float2* dB1 = drow0p + ((c + 1) & 1) * BUF_P + 128;
            dB1[sl0] = make_float2(r0v.y, r0v.x);   // odd b: swapped pairs
            dB1[sl1] = make_float2(r0v.w, r0v.z);
            dB1[sl2] = make_float2(r1v.y, r1v.x);
            dB1[sl3] = make_float2(r1v.w, r1v.z);
        }
        __syncthreads();
    }

    // ---- epilogue: transpose through smem (buffers are free now), RED.ADD to out ----
    // store: S2[b = lane][ o ^ lane ]; bank = (oo ^ lane) & 31 -> permutation per oo.
    float* S2 = S;   // 32 rows x 1024 floats = 128 KB
    #pragma unroll
    for (int oo = 0; oo < 32; ++oo)
        S2[lane * 1024 + ((obase + oo) ^ lane)] = acc[oo];
    __syncthreads();

    // warp wid sweeps b-row wid; reads bank (lane ^ wid) -> permutation; RED coalesced
    const float* row = S2 + wid * 1024;
    float* orow = out + (btile * BT + wid) * OUTF;
    #pragma unroll
    for (int t = 0; t < 32; ++t) {
        int o = t * 32 + lane;
        atomicAdd(orow + o, row[o ^ wid]);   // no return use -> RED.E.ADD.F32
    }
}

// ---------------- launch ----------------
extern "C" void kernel_launch(void* const* d_in, const int* in_sizes, int n_in,
                              void* d_out, int out_size) {
    const int*   inp = (const int*)d_in[0];    // input_indices  [512,32,4]
    const int*   wgt = (const int*)d_in[1];    // weight_indices [1024,32,4]
    const float* lut = (const float*)d_in[2];  // lut_table [256,256]
    float* out = (float*)d_out;

    // zero the poisoned output (512K floats = 128K float4)
    zero_out_kernel<<<(BATCH * OUTF / 4) / 256, 256>>>((float4*)out);

    const int smem_bytes = JT_U64 * 8 + 2 * BUF_F * 4;   // 16 KB + 128 KB
    cudaFuncSetAttribute(lut_main, cudaFuncAttributeMaxDynamicSharedMemorySize, smem_bytes);
    dim3 grid(BATCH / BT, NSEG);
    lut_main<<<grid, MTHREADS, smem_bytes>>>(inp, wgt, lut, out);
}